// round 10
// baseline (speedup 1.0000x reference)
#include <cuda_runtime.h>

// MMD loss in closed form over column statistics:
//   result = 7.75 * n(n-1) * ||Delta||^2 / ((n*S - ||M||^2) * B^2),  n = 2B
// Delta_c = colsum(s-t)_c, M_c = colsum(s+t)_c, S = sum(s^2)+sum(t^2).
// The (max-min) scale factor cancels exactly.
//
// 296 blocks x 512 threads (2 CTAs/SM, one wave): each thread does 2+2
// predicated float4 loads. Single-barrier block epilogue -> 4-way-banked
// f64 atomics. Handoff via one acq_rel atomic. Last block finalizes with
// the delta/msum reductions split across all 16 warps (halved shuffle
// chains) and a spare lane prefetching the sq accumulators.

#define NBLK 296
#define NTHR 512
#define DDIM 256
#define D4   64                      // DDIM / 4
#define STRIDE ((long)NBLK * NTHR)   // 151552, divisible by 64
#define NBANK 4

__device__ double g_delta[NBANK][DDIM];
__device__ double g_msum[NBANK][DDIM];
__device__ double g_sqb[NBANK];
__device__ unsigned int g_count;

__global__ __launch_bounds__(NTHR)
void mmd_fused(const float4* __restrict__ s4, const float4* __restrict__ t4,
               long N4, int B, float* __restrict__ out) {
    const int tid = threadIdx.x;
    const int c4  = tid & 63;    // float4 column group (STRIDE % 64 == 0)
    const int ro  = tid >> 6;    // 0..7

    // ---------------- Phase 1: streaming (2+2 loads) ----------------
    const long  base = (long)blockIdx.x * NTHR + tid;
    const float4 z4  = make_float4(0.f, 0.f, 0.f, 0.f);

    float4 as = z4, at = z4;
    float  sq = 0.f;

    if (N4 <= 2 * STRIDE) {
        const long e0 = base, e1 = base + STRIDE;
        float4 a0 = (e0 < N4) ? s4[e0] : z4;
        float4 a1 = (e1 < N4) ? s4[e1] : z4;
        float4 b0 = (e0 < N4) ? t4[e0] : z4;
        float4 b1 = (e1 < N4) ? t4[e1] : z4;

        as.x = a0.x + a1.x; as.y = a0.y + a1.y;
        as.z = a0.z + a1.z; as.w = a0.w + a1.w;
        at.x = b0.x + b1.x; at.y = b0.y + b1.y;
        at.z = b0.z + b1.z; at.w = b0.w + b1.w;

        sq = a0.x*a0.x + a0.y*a0.y + a0.z*a0.z + a0.w*a0.w
           + a1.x*a1.x + a1.y*a1.y + a1.z*a1.z + a1.w*a1.w
           + b0.x*b0.x + b0.y*b0.y + b0.z*b0.z + b0.w*b0.w
           + b1.x*b1.x + b1.y*b1.y + b1.z*b1.z + b1.w*b1.w;
    } else {
        for (long e = base; e < N4; e += STRIDE) {
            float4 v = s4[e];
            as.x += v.x; as.y += v.y; as.z += v.z; as.w += v.w;
            sq += v.x*v.x + v.y*v.y + v.z*v.z + v.w*v.w;
            float4 w = t4[e];
            at.x += w.x; at.y += w.y; at.z += w.z; at.w += w.w;
            sq += w.x*w.x + w.y*w.y + w.z*w.z + w.w*w.w;
        }
    }

    float4 ad, am;
    ad.x = as.x - at.x; ad.y = as.y - at.y; ad.z = as.z - at.z; ad.w = as.w - at.w;
    am.x = as.x + at.x; am.y = as.y + at.y; am.z = as.z + at.z; am.w = as.w + at.w;

    // ---------------- single-barrier block epilogue ----------------
    __shared__ float4 smd[8][64];
    __shared__ float4 smm[8][64];
    __shared__ float  smq[16];

    // STS first so the barrier-critical path doesn't wait on the shuffles
    smd[ro][c4] = ad;
    smm[ro][c4] = am;

    #pragma unroll
    for (int o = 16; o > 0; o >>= 1) sq += __shfl_down_sync(0xffffffffu, sq, o);
    if ((tid & 31) == 0) smq[tid >> 5] = sq;
    __syncthreads();

    const int bank = blockIdx.x & (NBANK - 1);
    if (tid < DDIM) {
        const float* fd = &reinterpret_cast<const float*>(smd)[tid];
        const float* fm = &reinterpret_cast<const float*>(smm)[tid];
        float d = 0.f, m = 0.f;
        #pragma unroll
        for (int g = 0; g < 8; g++) { d += fd[g * DDIM]; m += fm[g * DDIM]; }
        atomicAdd(&g_delta[bank][tid], (double)d);
        atomicAdd(&g_msum[bank][tid],  (double)m);
    } else if (tid == DDIM) {
        float q = 0.f;
        #pragma unroll
        for (int w = 0; w < 16; w++) q += smq[w];
        atomicAdd(&g_sqb[bank], (double)q);
    }

    // ---------------- handoff: acq_rel counter, no threadfence ----------
    __shared__ unsigned int lastFlag;
    __shared__ double sS;
    __syncthreads();   // all REDs issued; creates happens-before for release
    if (tid == 0) {
        unsigned int v;
        asm volatile("atom.add.acq_rel.gpu.u32 %0, [%1], 1;"
                     : "=r"(v) : "l"(&g_count) : "memory");
        lastFlag = (v == (unsigned)(NBLK - 1));
    }
    __syncthreads();
    if (!lastFlag) return;

    // ---------------- Phase 2: finalize (last block only) ----------------
    // warps 0..7: delta^2; warps 8..15: msum^2. One f64 per shuffle chain.
    __shared__ double wsum[16];   // wsum[0..7] = delta^2, wsum[8..15] = msum^2

    // spare lane fetches S (independent loads, overlapped)
    if (tid == 511) {
        sS = (g_sqb[0] + g_sqb[1]) + (g_sqb[2] + g_sqb[3]);
        g_sqb[0] = 0.0; g_sqb[1] = 0.0; g_sqb[2] = 0.0; g_sqb[3] = 0.0;
    }

    double acc;
    if (tid < DDIM) {
        double d = (g_delta[0][tid] + g_delta[1][tid])
                 + (g_delta[2][tid] + g_delta[3][tid]);
        acc = d * d;
        g_delta[0][tid] = 0.0; g_delta[1][tid] = 0.0;
        g_delta[2][tid] = 0.0; g_delta[3][tid] = 0.0;
    } else {
        const int c = tid - DDIM;
        double m = (g_msum[0][c] + g_msum[1][c])
                 + (g_msum[2][c] + g_msum[3][c]);
        acc = m * m;
        g_msum[0][c] = 0.0; g_msum[1][c] = 0.0;
        g_msum[2][c] = 0.0; g_msum[3][c] = 0.0;
    }
    #pragma unroll
    for (int o = 16; o > 0; o >>= 1)
        acc += __shfl_down_sync(0xffffffffu, acc, o);
    if ((tid & 31) == 0) wsum[tid >> 5] = acc;
    __syncthreads();

    if (tid < 16) {
        // lanes 0..7 carry delta^2 partials, lanes 8..15 carry msum^2.
        // Reducing d2 and m2 separately over 16 lanes leaves both sums on
        // lane 0 simultaneously.
        double d2 = (tid < 8)  ? wsum[tid] : 0.0;
        double m2 = (tid >= 8) ? wsum[tid] : 0.0;
        #pragma unroll
        for (int o = 8; o > 0; o >>= 1) {
            d2 += __shfl_down_sync(0xffffu, d2, o);
            m2 += __shfl_down_sync(0xffffu, m2, o);
        }
        if (tid == 0) {
            double n  = 2.0 * (double)B;
            double Bd = (double)B;
            double res = 7.75 * n * (n - 1.0) * d2
                       / ((n * sS - m2) * Bd * Bd);
            out[0] = (float)res;
            g_count = 0u;
        }
    }
}

extern "C" void kernel_launch(void* const* d_in, const int* in_sizes, int n_in,
                              void* d_out, int out_size) {
    const float* s = (const float*)d_in[0];
    const float* t = (const float*)d_in[1];
    int B = in_sizes[0] / DDIM;          // 4096 here
    long N4 = (long)B * D4;              // float4 count per array

    mmd_fused<<<NBLK, NTHR>>>((const float4*)s, (const float4*)t, N4, B,
                              (float*)d_out);
}